// round 1
// baseline (speedup 1.0000x reference)
#include <cuda_runtime.h>
#include <cstdint>
#include <cstddef>

// Problem constants
#define Bsz 4
#define Lsz 512
#define Dsz 768
#define Wsz 12
#define Ksz (Lsz * Wsz)      // 6144 spans per batch
#define NTOK (Bsz * Ksz)     // 24576 span tokens
#define BLROWS (Bsz * Lsz)   // 2048 h tokens
#define FFD 3072             // 4*D
#define CATD 1536            // 2*D

// Static device scratch (allocation-free rule)
__device__ float g_hidden[(size_t)NTOK * FFD];   // 75.5M floats (reused by all stages)
__device__ float g_start [(size_t)BLROWS * Dsz]; // start_rep
__device__ float g_end   [(size_t)BLROWS * Dsz]; // end_rep
__device__ float g_cat   [(size_t)NTOK * CATD];  // relu(concat) span features
__device__ int   g_is64;                         // span_idx dtype flag

// ---------------------------------------------------------------------------
// span_idx dtype detection: values are in [0,512). If stored as int64 (LE),
// every odd 32-bit word of the first NTOK*2 words is a zero high-half.
// If int32, odd words are uniform random indices -> essentially never all zero.
// Only reads the first B*K*2 32-bit words (safe for both dtypes).
// ---------------------------------------------------------------------------
__global__ void detect_idx_kernel(const unsigned int* __restrict__ sp, int nhalf) {
    __shared__ int s_any;
    if (threadIdx.x == 0) s_any = 0;
    __syncthreads();
    int found = 0;
    for (int i = threadIdx.x; i < nhalf; i += blockDim.x) {
        if (sp[2 * i + 1] != 0u) found = 1;
    }
    if (found) atomicOr(&s_any, 1);
    __syncthreads();
    if (threadIdx.x == 0) g_is64 = (s_any == 0) ? 1 : 0;
}

// ---------------------------------------------------------------------------
// SGEMM (NT): C[M,N] = A[M,K] * B[N,K]^T + bias[N], optional ReLU.
// Both A and B row-major, K contiguous. 128x128x16 tiles, 256 threads,
// 8x8 per-thread register tile, global->reg prefetch pipeline.
// Requires M%128==0, N%128==0, K%16==0 (holds for all call sites).
// ---------------------------------------------------------------------------
#define BM 128
#define BN 128
#define BK 16
#define TM 8
#define TN 8
#define SPAD 4

__global__ __launch_bounds__(256, 2)
void gemm_bias_kernel(const float* __restrict__ A,
                      const float* __restrict__ B,
                      const float* __restrict__ bias,
                      float* __restrict__ C,
                      int M, int N, int K, int doRelu)
{
    __shared__ float As[BK][BM + SPAD];
    __shared__ float Bs[BK][BN + SPAD];

    const int tid = threadIdx.x;
    const int bm = blockIdx.y * BM;
    const int bn = blockIdx.x * BN;

    const int tx = tid & 15;          // N direction
    const int ty = tid >> 4;          // M direction
    const int row0 = ty * TM;
    const int col0 = tx * TN;

    const float* Aptr = A + (size_t)bm * K;
    const float* Bptr = B + (size_t)bn * K;

    float acc[TM][TN];
#pragma unroll
    for (int i = 0; i < TM; i++)
#pragma unroll
        for (int j = 0; j < TN; j++) acc[i][j] = 0.f;

    float4 areg[2], breg[2];
    const int nk = K / BK;

    // Prologue: load tile 0
#pragma unroll
    for (int i = 0; i < 2; i++) {
        int f = tid + 256 * i;
        int m = f >> 2, kq = f & 3;
        areg[i] = *(const float4*)(Aptr + (size_t)m * K + kq * 4);
        breg[i] = *(const float4*)(Bptr + (size_t)m * K + kq * 4);
    }
#pragma unroll
    for (int i = 0; i < 2; i++) {
        int f = tid + 256 * i;
        int m = f >> 2, kq = f & 3;
        As[kq * 4 + 0][m] = areg[i].x; As[kq * 4 + 1][m] = areg[i].y;
        As[kq * 4 + 2][m] = areg[i].z; As[kq * 4 + 3][m] = areg[i].w;
        Bs[kq * 4 + 0][m] = breg[i].x; Bs[kq * 4 + 1][m] = breg[i].y;
        Bs[kq * 4 + 2][m] = breg[i].z; Bs[kq * 4 + 3][m] = breg[i].w;
    }
    __syncthreads();

    for (int kt = 0; kt < nk; kt++) {
        // Prefetch next K-tile into registers while computing current one
        if (kt + 1 < nk) {
            const float* An = Aptr + (size_t)(kt + 1) * BK;
            const float* Bn = Bptr + (size_t)(kt + 1) * BK;
#pragma unroll
            for (int i = 0; i < 2; i++) {
                int f = tid + 256 * i;
                int m = f >> 2, kq = f & 3;
                areg[i] = *(const float4*)(An + (size_t)m * K + kq * 4);
                breg[i] = *(const float4*)(Bn + (size_t)m * K + kq * 4);
            }
        }

#pragma unroll
        for (int kk = 0; kk < BK; kk++) {
            float4 a0 = *(const float4*)&As[kk][row0];
            float4 a1 = *(const float4*)&As[kk][row0 + 4];
            float4 b0 = *(const float4*)&Bs[kk][col0];
            float4 b1 = *(const float4*)&Bs[kk][col0 + 4];
            float a[TM] = {a0.x, a0.y, a0.z, a0.w, a1.x, a1.y, a1.z, a1.w};
            float b[TN] = {b0.x, b0.y, b0.z, b0.w, b1.x, b1.y, b1.z, b1.w};
#pragma unroll
            for (int i = 0; i < TM; i++)
#pragma unroll
                for (int j = 0; j < TN; j++)
                    acc[i][j] += a[i] * b[j];
        }
        __syncthreads();

        if (kt + 1 < nk) {
#pragma unroll
            for (int i = 0; i < 2; i++) {
                int f = tid + 256 * i;
                int m = f >> 2, kq = f & 3;
                As[kq * 4 + 0][m] = areg[i].x; As[kq * 4 + 1][m] = areg[i].y;
                As[kq * 4 + 2][m] = areg[i].z; As[kq * 4 + 3][m] = areg[i].w;
                Bs[kq * 4 + 0][m] = breg[i].x; Bs[kq * 4 + 1][m] = breg[i].y;
                Bs[kq * 4 + 2][m] = breg[i].z; Bs[kq * 4 + 3][m] = breg[i].w;
            }
            __syncthreads();
        }
    }

    // Epilogue: bias (+ optional ReLU), vectorized stores
    float bv[TN];
#pragma unroll
    for (int j = 0; j < TN; j++) bv[j] = bias[bn + col0 + j];

#pragma unroll
    for (int i = 0; i < TM; i++) {
        float v[TN];
#pragma unroll
        for (int j = 0; j < TN; j++) {
            v[j] = acc[i][j] + bv[j];
            if (doRelu) v[j] = fmaxf(v[j], 0.f);
        }
        float* crow = C + (size_t)(bm + row0 + i) * N + bn + col0;
        *(float4*)(crow)     = make_float4(v[0], v[1], v[2], v[3]);
        *(float4*)(crow + 4) = make_float4(v[4], v[5], v[6], v[7]);
    }
}

// ---------------------------------------------------------------------------
// Gather spans from start/end reps, concat, ReLU -> g_cat[NTOK, 2D]
// One thread per float4 of output. d-contiguous reads coalesce.
// ---------------------------------------------------------------------------
__global__ void gather_cat_kernel(const float* __restrict__ start_rep,
                                  const float* __restrict__ end_rep,
                                  const void* __restrict__ span,
                                  float* __restrict__ cat)
{
    const int QD = CATD / 4;  // 384 float4 per row
    int t = blockIdx.x * blockDim.x + threadIdx.x;
    if (t >= NTOK * QD) return;
    int r = t / QD;           // span token 0..24575
    int q = t - r * QD;
    int b = r / Ksz;
    int col = q * 4;

    int which = (col < Dsz) ? 0 : 1;
    size_t pos = (size_t)r * 2 + which;
    long long idx;
    if (g_is64) idx = ((const long long*)span)[pos];
    else        idx = (long long)((const int*)span)[pos];

    const float* base = which ? end_rep : start_rep;
    int d = which ? (col - Dsz) : col;
    const float* src = base + ((size_t)b * Lsz + idx) * Dsz + d;

    float4 v = *(const float4*)src;
    v.x = fmaxf(v.x, 0.f); v.y = fmaxf(v.y, 0.f);
    v.z = fmaxf(v.z, 0.f); v.w = fmaxf(v.w, 0.f);
    ((float4*)cat)[t] = v;
}

// ---------------------------------------------------------------------------
// Launch: h->start_rep, h->end_rep, gather+cat, cat->out MLP
// ---------------------------------------------------------------------------
extern "C" void kernel_launch(void* const* d_in, const int* in_sizes, int n_in,
                              void* d_out, int out_size)
{
    const float* h   = (const float*)d_in[0];
    const void*  sp  = d_in[1];
    const float* ws1 = (const float*)d_in[2];
    const float* bs1 = (const float*)d_in[3];
    const float* ws2 = (const float*)d_in[4];
    const float* bs2 = (const float*)d_in[5];
    const float* we1 = (const float*)d_in[6];
    const float* be1 = (const float*)d_in[7];
    const float* we2 = (const float*)d_in[8];
    const float* be2 = (const float*)d_in[9];
    const float* wo1 = (const float*)d_in[10];
    const float* bo1 = (const float*)d_in[11];
    const float* wo2 = (const float*)d_in[12];
    const float* bo2 = (const float*)d_in[13];
    float* out = (float*)d_out;

    float *hid, *st, *en, *cat;
    cudaGetSymbolAddress((void**)&hid, g_hidden);
    cudaGetSymbolAddress((void**)&st,  g_start);
    cudaGetSymbolAddress((void**)&en,  g_end);
    cudaGetSymbolAddress((void**)&cat, g_cat);

    detect_idx_kernel<<<1, 256>>>((const unsigned int*)sp, NTOK);

    // start MLP
    gemm_bias_kernel<<<dim3(FFD / BN, BLROWS / BM), 256>>>(h,   ws1, bs1, hid, BLROWS, FFD, Dsz, 1);
    gemm_bias_kernel<<<dim3(Dsz / BN, BLROWS / BM), 256>>>(hid, ws2, bs2, st,  BLROWS, Dsz, FFD, 0);
    // end MLP
    gemm_bias_kernel<<<dim3(FFD / BN, BLROWS / BM), 256>>>(h,   we1, be1, hid, BLROWS, FFD, Dsz, 1);
    gemm_bias_kernel<<<dim3(Dsz / BN, BLROWS / BM), 256>>>(hid, we2, be2, en,  BLROWS, Dsz, FFD, 0);

    // gather + concat + relu
    int gthreads = NTOK * (CATD / 4);
    gather_cat_kernel<<<(gthreads + 255) / 256, 256>>>(st, en, sp, cat);

    // output MLP (dominant cost)
    gemm_bias_kernel<<<dim3(FFD / BN, NTOK / BM), 256>>>(cat, wo1, bo1, hid, NTOK, FFD, CATD, 1);
    gemm_bias_kernel<<<dim3(Dsz / BN, NTOK / BM), 256>>>(hid, wo2, bo2, out, NTOK, Dsz, FFD, 0);
}

// round 2
// speedup vs baseline: 2.2012x; 2.2012x over previous
#include <cuda_runtime.h>
#include <cuda_bf16.h>
#include <cstdint>
#include <cstddef>

// Problem constants
#define Bsz 4
#define Lsz 512
#define Dsz 768
#define Wsz 12
#define Ksz (Lsz * Wsz)      // 6144 spans per batch
#define NTOK (Bsz * Ksz)     // 24576 span tokens
#define BLROWS (Bsz * Lsz)   // 2048 h tokens
#define FFD 3072             // 4*D
#define CATD 1536            // 2*D

// Static device scratch (allocation-free rule)
__device__ float g_hidden[(size_t)NTOK * FFD];
__device__ float g_start [(size_t)BLROWS * Dsz];
__device__ float g_end   [(size_t)BLROWS * Dsz];
__device__ float g_cat   [(size_t)NTOK * CATD];
__device__ int   g_is64;

// ---------------------------------------------------------------------------
// span_idx dtype detection (int64 vs int32), as in round 1.
// ---------------------------------------------------------------------------
__global__ void detect_idx_kernel(const unsigned int* __restrict__ sp, int nhalf) {
    __shared__ int s_any;
    if (threadIdx.x == 0) s_any = 0;
    __syncthreads();
    int found = 0;
    for (int i = threadIdx.x; i < nhalf; i += blockDim.x) {
        if (sp[2 * i + 1] != 0u) found = 1;
    }
    if (found) atomicOr(&s_any, 1);
    __syncthreads();
    if (threadIdx.x == 0) g_is64 = (s_any == 0) ? 1 : 0;
}

// ---------------------------------------------------------------------------
// PTX helpers
// ---------------------------------------------------------------------------
__device__ __forceinline__ uint32_t smem_u32(const void* p) {
    return (uint32_t)__cvta_generic_to_shared(p);
}
__device__ __forceinline__ void ldm_x4(uint32_t& r0, uint32_t& r1, uint32_t& r2, uint32_t& r3, uint32_t addr) {
    asm volatile("ldmatrix.sync.aligned.m8n8.x4.shared.b16 {%0,%1,%2,%3}, [%4];"
                 : "=r"(r0), "=r"(r1), "=r"(r2), "=r"(r3) : "r"(addr));
}
__device__ __forceinline__ void ldm_x2(uint32_t& r0, uint32_t& r1, uint32_t addr) {
    asm volatile("ldmatrix.sync.aligned.m8n8.x2.shared.b16 {%0,%1}, [%2];"
                 : "=r"(r0), "=r"(r1) : "r"(addr));
}
__device__ __forceinline__ void mma_bf16(float* d, const uint32_t* a, const uint32_t* b) {
    asm volatile(
        "mma.sync.aligned.m16n8k16.row.col.f32.bf16.bf16.f32 "
        "{%0,%1,%2,%3},{%4,%5,%6,%7},{%8,%9},{%0,%1,%2,%3};"
        : "+f"(d[0]), "+f"(d[1]), "+f"(d[2]), "+f"(d[3])
        : "r"(a[0]), "r"(a[1]), "r"(a[2]), "r"(a[3]), "r"(b[0]), "r"(b[1]));
}

// ---------------------------------------------------------------------------
// Split-precision bf16 tensor-core GEMM (NT):
//   C[M,N] = A[M,K] * B[N,K]^T + bias[N], optional ReLU.
// A,B fp32 row-major, K contiguous. In-kernel split x = hi + lo (bf16 each),
// acc += Ahi*Bhi + Ahi*Blo + Alo*Bhi (fp32 accum) -> ~1e-5 rel err.
// Block 128x128x32, 8 warps (2x4), warp tile 64x32, m16n8k16 mma.
// Requires M%128==0, N%128==0, K%32==0 (holds everywhere here).
// ---------------------------------------------------------------------------
#define BM 128
#define BN 128
#define BK 32
#define SK (BK + 8)   // padded smem row (bf16 elems): 80B rows, ldmatrix conflict-free

__global__ __launch_bounds__(256, 1)
void gemm_tc_kernel(const float* __restrict__ A,
                    const float* __restrict__ B,
                    const float* __restrict__ bias,
                    float* __restrict__ C,
                    int M, int N, int K, int doRelu)
{
    __shared__ __nv_bfloat16 sAh[BM][SK];
    __shared__ __nv_bfloat16 sAl[BM][SK];
    __shared__ __nv_bfloat16 sBh[BN][SK];
    __shared__ __nv_bfloat16 sBl[BN][SK];

    const int tid  = threadIdx.x;
    const int lane = tid & 31;
    const int wid  = tid >> 5;
    const int wm   = (wid >> 2) * 64;   // warp M offset (0 or 64)
    const int wn   = (wid & 3) * 32;    // warp N offset (0..96)

    const int bm = blockIdx.y * BM;
    const int bn = blockIdx.x * BN;

    const float* Aptr = A + (size_t)bm * K;
    const float* Bptr = B + (size_t)bn * K;

    float acc[4][4][4];
#pragma unroll
    for (int i = 0; i < 4; i++)
#pragma unroll
        for (int j = 0; j < 4; j++)
#pragma unroll
            for (int r = 0; r < 4; r++) acc[i][j][r] = 0.f;

    // ldmatrix lane address components
    const int aq    = lane >> 3;              // 0..3 (8x8 sub-matrix id)
    const int arow  = ((aq & 1) << 3) + (lane & 7);
    const int acol  = (aq >> 1) << 3;         // 0 or 8
    const int brow  = lane & 7;
    const int bcol  = ((lane >> 3) & 1) << 3; // 0 or 8 (lanes 16+ harmless dup)

    // Global prefetch: 4 float4 per thread per operand per BK-tile
    // flat f = tid + 256*i : row = f>>3 (0..127), colq = f&7 (float4 within 32 cols)
    float4 pa[4], pb[4];
    const int nk = K / BK;

    auto ldtile = [&](int kt) {
#pragma unroll
        for (int i = 0; i < 4; i++) {
            int f = tid + 256 * i;
            int r = f >> 3, cq = f & 7;
            pa[i] = *(const float4*)(Aptr + (size_t)r * K + kt * BK + cq * 4);
            pb[i] = *(const float4*)(Bptr + (size_t)r * K + kt * BK + cq * 4);
        }
    };
    auto sttile = [&]() {
#pragma unroll
        for (int i = 0; i < 4; i++) {
            int f = tid + 256 * i;
            int r = f >> 3, c = (f & 7) * 4;
            float x[4] = {pa[i].x, pa[i].y, pa[i].z, pa[i].w};
            float y[4] = {pb[i].x, pb[i].y, pb[i].z, pb[i].w};
            __nv_bfloat16 ah[4], al[4], bh[4], bl[4];
#pragma unroll
            for (int e = 0; e < 4; e++) {
                ah[e] = __float2bfloat16_rn(x[e]);
                al[e] = __float2bfloat16_rn(x[e] - __bfloat162float(ah[e]));
                bh[e] = __float2bfloat16_rn(y[e]);
                bl[e] = __float2bfloat16_rn(y[e] - __bfloat162float(bh[e]));
            }
            *(uint2*)&sAh[r][c] = *(uint2*)ah;
            *(uint2*)&sAl[r][c] = *(uint2*)al;
            *(uint2*)&sBh[r][c] = *(uint2*)bh;
            *(uint2*)&sBl[r][c] = *(uint2*)bl;
        }
    };

    ldtile(0);
    sttile();
    __syncthreads();

    for (int kt = 0; kt < nk; kt++) {
        if (kt + 1 < nk) ldtile(kt + 1);

#pragma unroll
        for (int kk = 0; kk < BK; kk += 16) {
            uint32_t ah[4][4], al[4][4], bh[4][2], bl[4][2];
#pragma unroll
            for (int mi = 0; mi < 4; mi++) {
                uint32_t adH = smem_u32(&sAh[wm + mi * 16 + arow][kk + acol]);
                uint32_t adL = smem_u32(&sAl[wm + mi * 16 + arow][kk + acol]);
                ldm_x4(ah[mi][0], ah[mi][1], ah[mi][2], ah[mi][3], adH);
                ldm_x4(al[mi][0], al[mi][1], al[mi][2], al[mi][3], adL);
            }
#pragma unroll
            for (int ni = 0; ni < 4; ni++) {
                uint32_t bdH = smem_u32(&sBh[wn + ni * 8 + brow][kk + bcol]);
                uint32_t bdL = smem_u32(&sBl[wn + ni * 8 + brow][kk + bcol]);
                ldm_x2(bh[ni][0], bh[ni][1], bdH);
                ldm_x2(bl[ni][0], bl[ni][1], bdL);
            }
#pragma unroll
            for (int mi = 0; mi < 4; mi++)
#pragma unroll
                for (int ni = 0; ni < 4; ni++) {
                    mma_bf16(acc[mi][ni], ah[mi], bh[ni]);
                    mma_bf16(acc[mi][ni], ah[mi], bl[ni]);
                    mma_bf16(acc[mi][ni], al[mi], bh[ni]);
                }
        }
        __syncthreads();

        if (kt + 1 < nk) {
            sttile();
            __syncthreads();
        }
    }

    // Epilogue: bias (+ReLU), float2 stores per mma accum fragment
    const int lr = lane >> 2;
    const int lc = (lane & 3) * 2;
#pragma unroll
    for (int mi = 0; mi < 4; mi++) {
#pragma unroll
        for (int ni = 0; ni < 4; ni++) {
            int gm = bm + wm + mi * 16 + lr;
            int gc = bn + wn + ni * 8 + lc;
            float b0 = bias[gc], b1 = bias[gc + 1];
            float v0 = acc[mi][ni][0] + b0;
            float v1 = acc[mi][ni][1] + b1;
            float v2 = acc[mi][ni][2] + b0;
            float v3 = acc[mi][ni][3] + b1;
            if (doRelu) {
                v0 = fmaxf(v0, 0.f); v1 = fmaxf(v1, 0.f);
                v2 = fmaxf(v2, 0.f); v3 = fmaxf(v3, 0.f);
            }
            *(float2*)(C + (size_t)gm * N + gc)       = make_float2(v0, v1);
            *(float2*)(C + (size_t)(gm + 8) * N + gc) = make_float2(v2, v3);
        }
    }
}

// ---------------------------------------------------------------------------
// Gather spans from start/end reps, concat, ReLU -> g_cat[NTOK, 2D]
// ---------------------------------------------------------------------------
__global__ void gather_cat_kernel(const float* __restrict__ start_rep,
                                  const float* __restrict__ end_rep,
                                  const void* __restrict__ span,
                                  float* __restrict__ cat)
{
    const int QD = CATD / 4;  // 384 float4 per row
    int t = blockIdx.x * blockDim.x + threadIdx.x;
    if (t >= NTOK * QD) return;
    int r = t / QD;
    int q = t - r * QD;
    int b = r / Ksz;
    int col = q * 4;

    int which = (col < Dsz) ? 0 : 1;
    size_t pos = (size_t)r * 2 + which;
    long long idx;
    if (g_is64) idx = ((const long long*)span)[pos];
    else        idx = (long long)((const int*)span)[pos];

    const float* base = which ? end_rep : start_rep;
    int d = which ? (col - Dsz) : col;
    const float* src = base + ((size_t)b * Lsz + idx) * Dsz + d;

    float4 v = *(const float4*)src;
    v.x = fmaxf(v.x, 0.f); v.y = fmaxf(v.y, 0.f);
    v.z = fmaxf(v.z, 0.f); v.w = fmaxf(v.w, 0.f);
    ((float4*)cat)[t] = v;
}

// ---------------------------------------------------------------------------
// Launch
// ---------------------------------------------------------------------------
extern "C" void kernel_launch(void* const* d_in, const int* in_sizes, int n_in,
                              void* d_out, int out_size)
{
    const float* h   = (const float*)d_in[0];
    const void*  sp  = d_in[1];
    const float* ws1 = (const float*)d_in[2];
    const float* bs1 = (const float*)d_in[3];
    const float* ws2 = (const float*)d_in[4];
    const float* bs2 = (const float*)d_in[5];
    const float* we1 = (const float*)d_in[6];
    const float* be1 = (const float*)d_in[7];
    const float* we2 = (const float*)d_in[8];
    const float* be2 = (const float*)d_in[9];
    const float* wo1 = (const float*)d_in[10];
    const float* bo1 = (const float*)d_in[11];
    const float* wo2 = (const float*)d_in[12];
    const float* bo2 = (const float*)d_in[13];
    float* out = (float*)d_out;

    float *hid, *st, *en, *cat;
    cudaGetSymbolAddress((void**)&hid, g_hidden);
    cudaGetSymbolAddress((void**)&st,  g_start);
    cudaGetSymbolAddress((void**)&en,  g_end);
    cudaGetSymbolAddress((void**)&cat, g_cat);

    detect_idx_kernel<<<1, 256>>>((const unsigned int*)sp, NTOK);

    // start MLP
    gemm_tc_kernel<<<dim3(FFD / BN, BLROWS / BM), 256>>>(h,   ws1, bs1, hid, BLROWS, FFD, Dsz, 1);
    gemm_tc_kernel<<<dim3(Dsz / BN, BLROWS / BM), 256>>>(hid, ws2, bs2, st,  BLROWS, Dsz, FFD, 0);
    // end MLP
    gemm_tc_kernel<<<dim3(FFD / BN, BLROWS / BM), 256>>>(h,   we1, be1, hid, BLROWS, FFD, Dsz, 1);
    gemm_tc_kernel<<<dim3(Dsz / BN, BLROWS / BM), 256>>>(hid, we2, be2, en,  BLROWS, Dsz, FFD, 0);

    // gather + concat + relu
    int gthreads = NTOK * (CATD / 4);
    gather_cat_kernel<<<(gthreads + 255) / 256, 256>>>(st, en, sp, cat);

    // output MLP (dominant cost)
    gemm_tc_kernel<<<dim3(FFD / BN, NTOK / BM), 256>>>(cat, wo1, bo1, hid, NTOK, FFD, CATD, 1);
    gemm_tc_kernel<<<dim3(Dsz / BN, NTOK / BM), 256>>>(hid, wo2, bo2, out, NTOK, Dsz, FFD, 0);
}

// round 4
// speedup vs baseline: 2.4724x; 1.1232x over previous
#include <cuda_runtime.h>
#include <cuda_bf16.h>
#include <cstdint>
#include <cstddef>

// Problem constants
#define Bsz 4
#define Lsz 512
#define Dsz 768
#define Wsz 12
#define Ksz (Lsz * Wsz)
#define NTOK (Bsz * Ksz)     // 24576
#define BLROWS (Bsz * Lsz)   // 2048
#define FFD 3072
#define CATD 1536

// Weight split-buffer offsets (elements)
#define OFF_WS1 0u
#define OFF_WS2 2359296u
#define OFF_WE1 4718592u
#define OFF_WE2 7077888u
#define OFF_WO1 9437184u
#define OFF_WO2 14155776u
#define WTOT    16515072u

// Static device scratch (allocation-free rule)
__device__ __nv_bfloat16 g_w_hi[WTOT];
__device__ __nv_bfloat16 g_w_lo[WTOT];
__device__ __nv_bfloat16 g_h_hi[(size_t)BLROWS * Dsz];
__device__ __nv_bfloat16 g_h_lo[(size_t)BLROWS * Dsz];
__device__ __nv_bfloat16 g_hid_hi[(size_t)NTOK * FFD];
__device__ __nv_bfloat16 g_hid_lo[(size_t)NTOK * FFD];
__device__ __nv_bfloat16 g_cat_hi[(size_t)NTOK * CATD];
__device__ __nv_bfloat16 g_cat_lo[(size_t)NTOK * CATD];
__device__ float g_start[(size_t)BLROWS * Dsz];
__device__ float g_end  [(size_t)BLROWS * Dsz];
__device__ int   g_is64;

// ---------------------------------------------------------------------------
// span_idx dtype detection (int64 vs int32)
// ---------------------------------------------------------------------------
__global__ void detect_idx_kernel(const unsigned int* __restrict__ sp, int nhalf) {
    __shared__ int s_any;
    if (threadIdx.x == 0) s_any = 0;
    __syncthreads();
    int found = 0;
    for (int i = threadIdx.x; i < nhalf; i += blockDim.x)
        if (sp[2 * i + 1] != 0u) found = 1;
    if (found) atomicOr(&s_any, 1);
    __syncthreads();
    if (threadIdx.x == 0) g_is64 = (s_any == 0) ? 1 : 0;
}

// ---------------------------------------------------------------------------
// fp32 -> (hi, lo) bf16 split, elementwise (vectorized by 4)
// ---------------------------------------------------------------------------
__global__ void split_kernel(const float* __restrict__ x,
                             __nv_bfloat16* __restrict__ hi,
                             __nv_bfloat16* __restrict__ lo, int n4)
{
    int t = blockIdx.x * blockDim.x + threadIdx.x;
    if (t >= n4) return;
    float4 v = ((const float4*)x)[t];
    __nv_bfloat162 h01 = __floats2bfloat162_rn(v.x, v.y);
    __nv_bfloat162 h23 = __floats2bfloat162_rn(v.z, v.w);
    __nv_bfloat162 l01 = __floats2bfloat162_rn(v.x - __low2float(h01), v.y - __high2float(h01));
    __nv_bfloat162 l23 = __floats2bfloat162_rn(v.z - __low2float(h23), v.w - __high2float(h23));
    ((uint2*)hi)[t] = make_uint2(*(uint32_t*)&h01, *(uint32_t*)&h23);
    ((uint2*)lo)[t] = make_uint2(*(uint32_t*)&l01, *(uint32_t*)&l23);
}

// ---------------------------------------------------------------------------
// PTX helpers
// ---------------------------------------------------------------------------
__device__ __forceinline__ uint32_t smem_u32(const void* p) {
    return (uint32_t)__cvta_generic_to_shared(p);
}
__device__ __forceinline__ void ldm_x4(uint32_t* r, uint32_t addr) {
    asm volatile("ldmatrix.sync.aligned.m8n8.x4.shared.b16 {%0,%1,%2,%3}, [%4];"
                 : "=r"(r[0]), "=r"(r[1]), "=r"(r[2]), "=r"(r[3]) : "r"(addr));
}
__device__ __forceinline__ void ldm_x2(uint32_t* r, uint32_t addr) {
    asm volatile("ldmatrix.sync.aligned.m8n8.x2.shared.b16 {%0,%1}, [%2];"
                 : "=r"(r[0]), "=r"(r[1]) : "r"(addr));
}
__device__ __forceinline__ void mma_bf16(float* d, const uint32_t* a, const uint32_t* b) {
    asm volatile(
        "mma.sync.aligned.m16n8k16.row.col.f32.bf16.bf16.f32 "
        "{%0,%1,%2,%3},{%4,%5,%6,%7},{%8,%9},{%0,%1,%2,%3};"
        : "+f"(d[0]), "+f"(d[1]), "+f"(d[2]), "+f"(d[3])
        : "r"(a[0]), "r"(a[1]), "r"(a[2]), "r"(a[3]), "r"(b[0]), "r"(b[1]));
}
__device__ __forceinline__ void cp16(uint32_t dst, const void* src) {
    asm volatile("cp.async.cg.shared.global [%0], [%1], 16;" :: "r"(dst), "l"(src));
}

// ---------------------------------------------------------------------------
// Split-bf16 tensor-core GEMM (NT): C = A*B^T + bias, 3 MMA passes.
// A,B pre-split bf16 (hi/lo), K-major. Block 128x128x32, cp.async 2-stage,
// 8 warps (2x4), warp tile 64x32. mode 0: fp32 C. mode 1: relu + split C.
// Requires M%128==0, N%128==0, K%32==0.
// ---------------------------------------------------------------------------
#define SKB    80                 // bytes per smem row (32 bf16 + 8 pad)
#define TILE_B (128 * SKB)        // 10240
#define STAGE_B (4 * TILE_B)      // 40960
#define SMEM_DYN (2 * STAGE_B)    // 81920

__global__ __launch_bounds__(256, 2)
void gemm_split_kernel(const __nv_bfloat16* __restrict__ Ah,
                       const __nv_bfloat16* __restrict__ Al,
                       const __nv_bfloat16* __restrict__ Bh,
                       const __nv_bfloat16* __restrict__ Bl,
                       const float* __restrict__ bias,
                       float* __restrict__ Cf,
                       __nv_bfloat16* __restrict__ Ch,
                       __nv_bfloat16* __restrict__ Cl,
                       int M, int N, int K, int mode)
{
    extern __shared__ char smem[];
    const uint32_t sbase = smem_u32(smem);

    const int tid  = threadIdx.x;
    const int lane = tid & 31;
    const int wid  = tid >> 5;
    const int wm   = (wid >> 2) * 64;
    const int wn   = (wid & 3) * 32;
    const int bm   = blockIdx.y << 7;
    const int bn   = blockIdx.x << 7;

    float acc[4][4][4];
#pragma unroll
    for (int i = 0; i < 4; i++)
#pragma unroll
        for (int j = 0; j < 4; j++)
#pragma unroll
            for (int r = 0; r < 4; r++) acc[i][j][r] = 0.f;

    // cp.async geometry: per stage 4 tiles x 128 rows x 64B (4x16B chunks)
    const int crow = tid >> 2;           // 0..63
    const int cchk = (tid & 3) * 8;      // bf16 offset of 16B chunk in row
    const uint32_t drow = (uint32_t)(tid >> 2) * SKB + (tid & 3) * 16;

    const __nv_bfloat16* tsrc[4] = {
        Ah + (size_t)bm * K, Al + (size_t)bm * K,
        Bh + (size_t)bn * K, Bl + (size_t)bn * K };

    const int nk = K >> 5;

    auto issue = [&](int kt) {
        const int s = kt & 1;
        const int kb = kt << 5;
        uint32_t d0 = sbase + s * STAGE_B + drow;
#pragma unroll
        for (int i = 0; i < 8; i++) {
            const int t = i >> 1;
            const int r = (i & 1) * 64 + crow;
            cp16(d0 + t * TILE_B + (i & 1) * (64 * SKB),
                 tsrc[t] + (size_t)r * K + kb + cchk);
        }
    };

    // ldmatrix lane mapping
    const int aq   = lane >> 3;
    const int arow = ((aq & 1) << 3) + (lane & 7);
    const int acol = (aq >> 1) << 3;
    const int brow = lane & 7;
    const int bcol = ((lane >> 3) & 1) << 3;

    issue(0);
    asm volatile("cp.async.commit_group;" ::: "memory");

    for (int kt = 0; kt < nk; kt++) {
        asm volatile("cp.async.wait_group 0;" ::: "memory");
        __syncthreads();
        if (kt + 1 < nk) issue(kt + 1);
        asm volatile("cp.async.commit_group;" ::: "memory");

        const uint32_t st = sbase + (kt & 1) * STAGE_B;
        const uint32_t sAh = st;
        const uint32_t sAl = st + TILE_B;
        const uint32_t sBh = st + 2 * TILE_B;
        const uint32_t sBl = st + 3 * TILE_B;

#pragma unroll
        for (int kk = 0; kk < 32; kk += 16) {
            uint32_t ah[4][4], al[4][4], bh[4][2], bl[4][2];
#pragma unroll
            for (int mi = 0; mi < 4; mi++) {
                uint32_t off = (uint32_t)(wm + mi * 16 + arow) * SKB + (kk + acol) * 2;
                ldm_x4(ah[mi], sAh + off);
                ldm_x4(al[mi], sAl + off);
            }
#pragma unroll
            for (int ni = 0; ni < 4; ni++) {
                uint32_t off = (uint32_t)(wn + ni * 8 + brow) * SKB + (kk + bcol) * 2;
                ldm_x2(bh[ni], sBh + off);
                ldm_x2(bl[ni], sBl + off);
            }
#pragma unroll
            for (int mi = 0; mi < 4; mi++)
#pragma unroll
                for (int ni = 0; ni < 4; ni++) {
                    mma_bf16(acc[mi][ni], ah[mi], bh[ni]);
                    mma_bf16(acc[mi][ni], ah[mi], bl[ni]);
                    mma_bf16(acc[mi][ni], al[mi], bh[ni]);
                }
        }
    }

    // Epilogue
    const int lr = lane >> 2;
    const int lc = (lane & 3) * 2;
#pragma unroll
    for (int mi = 0; mi < 4; mi++) {
#pragma unroll
        for (int ni = 0; ni < 4; ni++) {
            const int gm = bm + wm + mi * 16 + lr;
            const int gc = bn + wn + ni * 8 + lc;
            const float b0 = bias[gc], b1 = bias[gc + 1];
            float v0 = acc[mi][ni][0] + b0;
            float v1 = acc[mi][ni][1] + b1;
            float v2 = acc[mi][ni][2] + b0;
            float v3 = acc[mi][ni][3] + b1;
            if (mode == 0) {
                *(float2*)(Cf + (size_t)gm * N + gc)       = make_float2(v0, v1);
                *(float2*)(Cf + (size_t)(gm + 8) * N + gc) = make_float2(v2, v3);
            } else {
                v0 = fmaxf(v0, 0.f); v1 = fmaxf(v1, 0.f);
                v2 = fmaxf(v2, 0.f); v3 = fmaxf(v3, 0.f);
                __nv_bfloat162 h01 = __floats2bfloat162_rn(v0, v1);
                __nv_bfloat162 h23 = __floats2bfloat162_rn(v2, v3);
                __nv_bfloat162 l01 = __floats2bfloat162_rn(v0 - __low2float(h01), v1 - __high2float(h01));
                __nv_bfloat162 l23 = __floats2bfloat162_rn(v2 - __low2float(h23), v3 - __high2float(h23));
                *(uint32_t*)(Ch + (size_t)gm * N + gc)       = *(uint32_t*)&h01;
                *(uint32_t*)(Cl + (size_t)gm * N + gc)       = *(uint32_t*)&l01;
                *(uint32_t*)(Ch + (size_t)(gm + 8) * N + gc) = *(uint32_t*)&h23;
                *(uint32_t*)(Cl + (size_t)(gm + 8) * N + gc) = *(uint32_t*)&l23;
            }
        }
    }
}

// ---------------------------------------------------------------------------
// Gather spans, concat, ReLU, split -> cat_hi/cat_lo [NTOK, 2D]
// ---------------------------------------------------------------------------
__global__ void gather_cat_kernel(const float* __restrict__ start_rep,
                                  const float* __restrict__ end_rep,
                                  const void* __restrict__ span,
                                  __nv_bfloat16* __restrict__ cat_hi,
                                  __nv_bfloat16* __restrict__ cat_lo)
{
    const int QD = CATD / 4;
    int t = blockIdx.x * blockDim.x + threadIdx.x;
    if (t >= NTOK * QD) return;
    int r = t / QD;
    int q = t - r * QD;
    int b = r / Ksz;
    int col = q * 4;

    int which = (col < Dsz) ? 0 : 1;
    size_t pos = (size_t)r * 2 + which;
    long long idx;
    if (g_is64) idx = ((const long long*)span)[pos];
    else        idx = (long long)((const int*)span)[pos];

    const float* base = which ? end_rep : start_rep;
    int d = which ? (col - Dsz) : col;
    const float* src = base + ((size_t)b * Lsz + idx) * Dsz + d;

    float4 v = *(const float4*)src;
    v.x = fmaxf(v.x, 0.f); v.y = fmaxf(v.y, 0.f);
    v.z = fmaxf(v.z, 0.f); v.w = fmaxf(v.w, 0.f);

    __nv_bfloat162 h01 = __floats2bfloat162_rn(v.x, v.y);
    __nv_bfloat162 h23 = __floats2bfloat162_rn(v.z, v.w);
    __nv_bfloat162 l01 = __floats2bfloat162_rn(v.x - __low2float(h01), v.y - __high2float(h01));
    __nv_bfloat162 l23 = __floats2bfloat162_rn(v.z - __low2float(h23), v.w - __high2float(h23));
    ((uint2*)cat_hi)[t] = make_uint2(*(uint32_t*)&h01, *(uint32_t*)&h23);
    ((uint2*)cat_lo)[t] = make_uint2(*(uint32_t*)&l01, *(uint32_t*)&l23);
}

// ---------------------------------------------------------------------------
// Launch
// ---------------------------------------------------------------------------
extern "C" void kernel_launch(void* const* d_in, const int* in_sizes, int n_in,
                              void* d_out, int out_size)
{
    const float* h   = (const float*)d_in[0];
    const void*  sp  = d_in[1];
    const float* ws1 = (const float*)d_in[2];
    const float* bs1 = (const float*)d_in[3];
    const float* ws2 = (const float*)d_in[4];
    const float* bs2 = (const float*)d_in[5];
    const float* we1 = (const float*)d_in[6];
    const float* be1 = (const float*)d_in[7];
    const float* we2 = (const float*)d_in[8];
    const float* be2 = (const float*)d_in[9];
    const float* wo1 = (const float*)d_in[10];
    const float* bo1 = (const float*)d_in[11];
    const float* wo2 = (const float*)d_in[12];
    const float* bo2 = (const float*)d_in[13];
    float* out = (float*)d_out;

    __nv_bfloat16 *whi, *wlo, *hhi, *hlo, *dhhi, *dhlo, *chi, *clo;
    float *st, *en;
    cudaGetSymbolAddress((void**)&whi,  g_w_hi);
    cudaGetSymbolAddress((void**)&wlo,  g_w_lo);
    cudaGetSymbolAddress((void**)&hhi,  g_h_hi);
    cudaGetSymbolAddress((void**)&hlo,  g_h_lo);
    cudaGetSymbolAddress((void**)&dhhi, g_hid_hi);
    cudaGetSymbolAddress((void**)&dhlo, g_hid_lo);
    cudaGetSymbolAddress((void**)&chi,  g_cat_hi);
    cudaGetSymbolAddress((void**)&clo,  g_cat_lo);
    cudaGetSymbolAddress((void**)&st,   g_start);
    cudaGetSymbolAddress((void**)&en,   g_end);

    cudaFuncSetAttribute(gemm_split_kernel,
                         cudaFuncAttributeMaxDynamicSharedMemorySize, SMEM_DYN);

    detect_idx_kernel<<<1, 256>>>((const unsigned int*)sp, NTOK);

    // Pre-split h and weights into bf16 hi/lo
    {
        int n4;
        n4 = (BLROWS * Dsz) / 4;
        split_kernel<<<(n4 + 255) / 256, 256>>>(h, hhi, hlo, n4);
        n4 = (FFD * Dsz) / 4;
        split_kernel<<<(n4 + 255) / 256, 256>>>(ws1, whi + OFF_WS1, wlo + OFF_WS1, n4);
        split_kernel<<<(n4 + 255) / 256, 256>>>(we1, whi + OFF_WE1, wlo + OFF_WE1, n4);
        n4 = (Dsz * FFD) / 4;
        split_kernel<<<(n4 + 255) / 256, 256>>>(ws2, whi + OFF_WS2, wlo + OFF_WS2, n4);
        split_kernel<<<(n4 + 255) / 256, 256>>>(we2, whi + OFF_WE2, wlo + OFF_WE2, n4);
        n4 = (FFD * CATD) / 4;
        split_kernel<<<(n4 + 255) / 256, 256>>>(wo1, whi + OFF_WO1, wlo + OFF_WO1, n4);
        n4 = (Dsz * FFD) / 4;
        split_kernel<<<(n4 + 255) / 256, 256>>>(wo2, whi + OFF_WO2, wlo + OFF_WO2, n4);
    }

    // start MLP
    gemm_split_kernel<<<dim3(FFD/128, BLROWS/128), 256, SMEM_DYN>>>(
        hhi, hlo, whi + OFF_WS1, wlo + OFF_WS1, bs1, nullptr, dhhi, dhlo,
        BLROWS, FFD, Dsz, 1);
    gemm_split_kernel<<<dim3(Dsz/128, BLROWS/128), 256, SMEM_DYN>>>(
        dhhi, dhlo, whi + OFF_WS2, wlo + OFF_WS2, bs2, st, nullptr, nullptr,
        BLROWS, Dsz, FFD, 0);
    // end MLP
    gemm_split_kernel<<<dim3(FFD/128, BLROWS/128), 256, SMEM_DYN>>>(
        hhi, hlo, whi + OFF_WE1, wlo + OFF_WE1, be1, nullptr, dhhi, dhlo,
        BLROWS, FFD, Dsz, 1);
    gemm_split_kernel<<<dim3(Dsz/128, BLROWS/128), 256, SMEM_DYN>>>(
        dhhi, dhlo, whi + OFF_WE2, wlo + OFF_WE2, be2, en, nullptr, nullptr,
        BLROWS, Dsz, FFD, 0);

    // gather + concat + relu + split
    int gthreads = NTOK * (CATD / 4);
    gather_cat_kernel<<<(gthreads + 255) / 256, 256>>>(st, en, sp, chi, clo);

    // output MLP (dominant)
    gemm_split_kernel<<<dim3(FFD/128, NTOK/128), 256, SMEM_DYN>>>(
        chi, clo, whi + OFF_WO1, wlo + OFF_WO1, bo1, nullptr, dhhi, dhlo,
        NTOK, FFD, CATD, 1);
    gemm_split_kernel<<<dim3(Dsz/128, NTOK/128), 256, SMEM_DYN>>>(
        dhhi, dhlo, whi + OFF_WO2, wlo + OFF_WO2, bo2, out, nullptr, nullptr,
        NTOK, Dsz, FFD, 0);
}